// round 17
// baseline (speedup 1.0000x reference)
#include <cuda_runtime.h>
#include <cuda_bf16.h>
#include <cuda_fp16.h>
#include <cstdint>
#include <cstddef>

#define DIMC   384
#define HEADS  12
#define HD     32
#define NTOK   49
#define BWIN   4096
#define NWIN   256
#define MROWS  (BWIN * NTOK)
#define QKVN   (3 * DIMC)
#define QSCALE 0.17677669529663687f

__device__ __half g_q16[(size_t)MROWS * QKVN];         // qkv fp16 (q pre-scaled)
__device__ __half g_x16[(size_t)MROWS * DIMC];         // x as fp16
__device__ __half g_a16[(size_t)MROWS * DIMC];         // attn out as fp16
__device__ __half g_w16[(size_t)(QKVN + DIMC) * DIMC]; // W^T fp16
__device__ float g_comb[(size_t)NWIN * HEADS * NTOK * 64 + 4096];

__device__ __forceinline__ uint32_t smem_u32(const void* p) {
    uint32_t a;
    asm("{ .reg .u64 t; cvta.to.shared.u64 t, %1; cvt.u32.u64 %0, t; }"
        : "=r"(a) : "l"(p));
    return a;
}
__device__ __forceinline__ uint32_t sw128(uint32_t off) {
    return off ^ ((off >> 3) & 0x70);
}
__device__ __forceinline__ void ldsm4(uint32_t (&r)[4], uint32_t addr) {
    asm volatile("ldmatrix.sync.aligned.m8n8.x4.shared.b16 {%0,%1,%2,%3}, [%4];"
        : "=r"(r[0]), "=r"(r[1]), "=r"(r[2]), "=r"(r[3]) : "r"(addr));
}
__device__ __forceinline__ void ldsm4t(uint32_t (&r)[4], uint32_t addr) {
    asm volatile("ldmatrix.sync.aligned.m8n8.x4.trans.shared.b16 {%0,%1,%2,%3}, [%4];"
        : "=r"(r[0]), "=r"(r[1]), "=r"(r[2]), "=r"(r[3]) : "r"(addr));
}
__device__ __forceinline__ void mma_f16(float (&d)[4], const uint32_t (&a)[4],
                                        uint32_t b0, uint32_t b1) {
    asm volatile(
        "mma.sync.aligned.m16n8k16.row.col.f32.f16.f16.f32 "
        "{%0,%1,%2,%3}, {%4,%5,%6,%7}, {%8,%9}, {%0,%1,%2,%3};"
        : "+f"(d[0]), "+f"(d[1]), "+f"(d[2]), "+f"(d[3])
        : "r"(a[0]), "r"(a[1]), "r"(a[2]), "r"(a[3]), "r"(b0), "r"(b1));
}
__device__ __forceinline__ void cp16(uint32_t dst, const void* src) {
    asm volatile("cp.async.cg.shared.global [%0], [%1], 16;"
                 :: "r"(dst), "l"(src));
}
#define CP_COMMIT() asm volatile("cp.async.commit_group;" ::: "memory")
#define CP_WAIT0()  asm volatile("cp.async.wait_group 0;" ::: "memory")

// ------------------------------- prep kernels -------------------------------
__global__ void prep_w_kernel(const float* __restrict__ W,
                              __half* __restrict__ w16, int K, int N) {
    int idx = blockIdx.x * blockDim.x + threadIdx.x;
    if (idx >= N * K) return;
    int n = idx / K, k = idx % K;
    w16[idx] = __float2half_rn(W[(size_t)k * N + n]);
}

__global__ void prep_x_kernel(const float* __restrict__ x,
                              __half* __restrict__ x16, size_t n4) {
    size_t i = (size_t)blockIdx.x * blockDim.x + threadIdx.x;
    if (i >= n4) return;
    float4 xv = ((const float4*)x)[i];
    __half2 a = __floats2half2_rn(xv.x, xv.y);
    __half2 b = __floats2half2_rn(xv.z, xv.w);
    ((uint2*)x16)[i] = make_uint2(*(uint32_t*)&a, *(uint32_t*)&b);
}

// comb[w][h][R][C64] = mask[w][R][C] + clip(bias,+-5); 0 for C>=49
__global__ void prep_comb_kernel(const float* __restrict__ mask,
                                 const float* __restrict__ table,
                                 const int* __restrict__ idx,
                                 float* __restrict__ out) {
    int e = blockIdx.x * blockDim.x + threadIdx.x;
    if (e >= NWIN * HEADS * NTOK * 64) return;
    int C = e & 63, R = (e >> 6) % NTOK;
    int wh = e / (NTOK * 64);
    int w = wh / HEADS, h = wh % HEADS;
    float v = 0.f;
    if (C < NTOK) {
        float b = table[idx[R * NTOK + C] * HEADS + h];
        v = mask[(size_t)w * NTOK * NTOK + R * NTOK + C]
          + fminf(fmaxf(b, -5.f), 5.f);
    }
    out[e] = v;
}

// ---- fp16 GEMM: C = A @ Wt^T + bias. 1 MMA per tile.
// BM=BN=128, BK=64, 2-stage double buffer; 64KB/CTA -> 3 CTAs/SM.
#define GEMM_SMEM_BYTES (2 * 32768)

template <bool QKV, bool H16OUT>
__global__ __launch_bounds__(256, 3) void mma_gemm(
    const __half* __restrict__ A16, const __half* __restrict__ B16,
    const float* __restrict__ bias, float* __restrict__ C,
    __half* __restrict__ C16,
    int M, int N, int K)
{
    extern __shared__ char smem[];
    const uint32_t sb = smem_u32(smem);
    const int tid = threadIdx.x, lane = tid & 31, wid = tid >> 5;
    const int wm = wid & 3, wn = wid >> 2;
    const int bm = blockIdx.y * 128, bn = blockIdx.x * 128;
    const int NCH = K / 64;            // 6
    const int crow = tid >> 3, cpos = tid & 7;

    auto cp_stage = [&](int s, int ch) {
        const int k0 = ch * 64;
        const uint32_t st = sb + s * 32768;
        #pragma unroll
        for (int t = 0; t < 4; t++) {
            const int row = t * 32 + crow;
            const uint32_t soff = sw128((uint32_t)(row * 128 + cpos * 16));
            const size_t ga = (size_t)(bm + row) * K + k0 + cpos * 8;
            const size_t gb = (size_t)(bn + row) * K + k0 + cpos * 8;
            cp16(st + soff,         A16 + ga);
            cp16(st + 16384 + soff, B16 + gb);
        }
    };

    float acc[2][8][4] = {};

    auto domma = [&](int s) {
        const uint32_t sA = sb + s * 32768;
        const uint32_t sB = sA + 16384;
        #pragma unroll
        for (int ks = 0; ks < 4; ks++) {
            const int cb = ks * 32 + (lane >> 4) * 16;
            uint32_t af[2][4];
            #pragma unroll
            for (int mt = 0; mt < 2; mt++) {
                const int r = wm * 32 + mt * 16 + (lane & 15);
                ldsm4(af[mt], sA + sw128((uint32_t)(r * 128 + cb)));
            }
            uint32_t bf[4][4];
            #pragma unroll
            for (int g = 0; g < 4; g++) {
                const int r = wn * 64 + g * 16 + (lane & 15);
                ldsm4(bf[g], sB + sw128((uint32_t)(r * 128 + cb)));
            }
            #pragma unroll
            for (int mt = 0; mt < 2; mt++)
                #pragma unroll
                for (int nt = 0; nt < 8; nt++) {
                    const int g = nt >> 1, o = nt & 1;
                    mma_f16(acc[mt][nt], af[mt], bf[g][o], bf[g][o + 2]);
                }
        }
    };

    // 2-stage: preload chunk 0; per iter: wait, sync, prefetch ch+1, compute ch
    cp_stage(0, 0); CP_COMMIT();
    for (int ch = 0; ch < NCH; ch++) {
        const int s = ch & 1;
        CP_WAIT0();             // chunk ch resident (overlapped domma(ch-1))
        __syncthreads();        // all warps done reading buffer s^1
        if (ch + 1 < NCH) cp_stage(s ^ 1, ch + 1);
        CP_COMMIT();
        domma(s);
    }

    const float qs = (QKV && bn < DIMC) ? QSCALE : 1.0f;
    #pragma unroll
    for (int mt = 0; mt < 2; mt++) {
        const int r0 = bm + wm * 32 + mt * 16 + (lane >> 2);
        #pragma unroll
        for (int nt = 0; nt < 8; nt++) {
            const int c0 = bn + wn * 64 + nt * 8 + (lane & 3) * 2;
            const float2 bv = *(const float2*)(bias + c0);
            float x0 = (acc[mt][nt][0] + bv.x) * qs;
            float y0 = (acc[mt][nt][1] + bv.y) * qs;
            float x1 = (acc[mt][nt][2] + bv.x) * qs;
            float y1 = (acc[mt][nt][3] + bv.y) * qs;
            if (H16OUT) {
                __half2 h0 = __floats2half2_rn(x0, y0);
                __half2 h1 = __floats2half2_rn(x1, y1);
                *(uint32_t*)(C16 + (size_t)r0 * N + c0)       = *(uint32_t*)&h0;
                *(uint32_t*)(C16 + (size_t)(r0 + 8) * N + c0) = *(uint32_t*)&h1;
            } else {
                *(float2*)(C + (size_t)r0 * N + c0)       = make_float2(x0, y0);
                *(float2*)(C + (size_t)(r0 + 8) * N + c0) = make_float2(x1, y1);
            }
        }
    }
}

// ---------------- Attention (unchanged from R15) ----------------------------
#define ATTN_SMEM_BYTES (3 * 16384)

__global__ __launch_bounds__(128, 2) void attn_mma_kernel(
    const __half* __restrict__ q16_g,
    const float* __restrict__ comb, __half* __restrict__ o16)
{
    extern __shared__ char smem[];
    const uint32_t sb = smem_u32(smem);
    const int tid = threadIdx.x, lane = tid & 31, wid = tid >> 5;
    const int b = blockIdx.x / 3, hg = blockIdx.x % 3;
    const int h = hg * 4 + wid;

    for (int i = tid; i < 6 * 15 * 8; i += 128) {
        const int t = i / 120, rr = 49 + (i % 120) / 8, q4 = i % 8;
        *(uint4*)(smem + t * 8192 + sw128((uint32_t)(rr * 128 + q4 * 16))) =
            make_uint4(0, 0, 0, 0);
    }
    {
        const size_t rowbase = (size_t)b * NTOK * QKVN;
        for (int i = tid; i < NTOK * 48; i += 128) {
            const int n = i / 48, rem = i % 48;
            const int mat = rem >> 4, ck = rem & 15;
            const __half* src = q16_g + rowbase + (size_t)n * QKVN
                              + mat * DIMC + hg * 128 + ck * 8;
            const uint32_t dst = sb + mat * 16384 + (ck >> 3) * 8192
                               + sw128((uint32_t)(n * 128 + (ck & 7) * 16));
            cp16(dst, src);
        }
    }
    CP_COMMIT(); CP_WAIT0();
    __syncthreads();

    const int t = wid >> 1, th = wid & 1;
    const uint32_t Qm = sb + t * 8192;
    const uint32_t Km = Qm + 16384, Vm = Qm + 32768;

    float acc[4][7][4] = {};
    #pragma unroll
    for (int ks = 0; ks < 2; ks++) {
        const uint32_t qb = (uint32_t)(th * 64 + (2 * ks + (lane >> 4)) * 16);
        uint32_t qf[4][4];
        #pragma unroll
        for (int mt = 0; mt < 4; mt++) {
            const int r = mt * 16 + (lane & 15);
            ldsm4(qf[mt], Qm + sw128((uint32_t)(r * 128) + qb));
        }
        #pragma unroll
        for (int g = 0; g < 4; g++) {
            const int rk = g * 16 + (lane & 15);
            uint32_t kf[4];
            ldsm4(kf, Km + sw128((uint32_t)(rk * 128) + qb));
            #pragma unroll
            for (int o = 0; o < 2; o++) {
                const int nt = g * 2 + o;
                if (nt == 7) continue;
                #pragma unroll
                for (int mt = 0; mt < 4; mt++)
                    mma_f16(acc[mt][nt], qf[mt], kf[o], kf[o + 2]);
            }
        }
    }

    const float* cw = comb + ((size_t)(b & (NWIN - 1)) * HEADS + h) * (NTOK * 64);
    #pragma unroll
    for (int mt = 0; mt < 4; mt++)
        #pragma unroll
        for (int nt = 0; nt < 7; nt++) {
            const int C0 = nt * 8 + 2 * (lane & 3);
            #pragma unroll
            for (int rh = 0; rh < 2; rh++) {
                const int R = mt * 16 + (lane >> 2) + rh * 8;
                const float2 cb = *(const float2*)(cw + R * 64 + C0);
                float s0 = fminf(fmaxf(acc[mt][nt][rh*2]   + cb.x, -10.f), 10.f);
                float s1 = fminf(fmaxf(acc[mt][nt][rh*2+1] + cb.y, -10.f), 10.f);
                if (nt == 6) {
                    if (C0 >= NTOK)     s0 = -1e30f;
                    if (C0 + 1 >= NTOK) s1 = -1e30f;
                }
                acc[mt][nt][rh*2]   = s0;
                acc[mt][nt][rh*2+1] = s1;
            }
        }

    #pragma unroll
    for (int mt = 0; mt < 4; mt++)
        #pragma unroll
        for (int rh = 0; rh < 2; rh++) {
            float mx = -1e30f;
            #pragma unroll
            for (int nt = 0; nt < 7; nt++)
                mx = fmaxf(mx, fmaxf(acc[mt][nt][rh*2], acc[mt][nt][rh*2+1]));
            mx = fmaxf(mx, __shfl_xor_sync(0xffffffffu, mx, 1));
            mx = fmaxf(mx, __shfl_xor_sync(0xffffffffu, mx, 2));
            float sum = 0.f;
            #pragma unroll
            for (int nt = 0; nt < 7; nt++) {
                float e0 = __expf(acc[mt][nt][rh*2]   - mx);
                float e1 = __expf(acc[mt][nt][rh*2+1] - mx);
                acc[mt][nt][rh*2] = e0; acc[mt][nt][rh*2+1] = e1;
                sum += e0 + e1;
            }
            sum += __shfl_xor_sync(0xffffffffu, sum, 1);
            sum += __shfl_xor_sync(0xffffffffu, sum, 2);
            const float inv = 1.f / sum;
            #pragma unroll
            for (int nt = 0; nt < 7; nt++) {
                acc[mt][nt][rh*2] *= inv; acc[mt][nt][rh*2+1] *= inv;
            }
        }

    float oacc[4][4][4] = {};
    #pragma unroll
    for (int kk = 0; kk < 4; kk++) {
        uint32_t vf[2][4];
        #pragma unroll
        for (int dp = 0; dp < 2; dp++) {
            const int rm = kk * 16 + (lane & 15);
            const uint32_t vb = (uint32_t)(th * 64 + dp * 32 + (lane >> 4) * 16);
            ldsm4t(vf[dp], Vm + sw128((uint32_t)(rm * 128) + vb));
        }
        const int nta = kk * 2, ntb = kk * 2 + 1;
        #pragma unroll
        for (int mt = 0; mt < 4; mt++) {
            uint32_t ph[4];
            __half2 p0 = __floats2half2_rn(acc[mt][nta][0], acc[mt][nta][1]);
            __half2 p1 = __floats2half2_rn(acc[mt][nta][2], acc[mt][nta][3]);
            ph[0] = *(uint32_t*)&p0;
            ph[1] = *(uint32_t*)&p1;
            if (ntb < 7) {
                __half2 p2 = __floats2half2_rn(acc[mt][ntb][0], acc[mt][ntb][1]);
                __half2 p3 = __floats2half2_rn(acc[mt][ntb][2], acc[mt][ntb][3]);
                ph[2] = *(uint32_t*)&p2;
                ph[3] = *(uint32_t*)&p3;
            } else {
                ph[2] = ph[3] = 0u;
            }
            #pragma unroll
            for (int dp = 0; dp < 2; dp++)
                #pragma unroll
                for (int o = 0; o < 2; o++) {
                    const int dt = dp * 2 + o;
                    mma_f16(oacc[mt][dt], ph, vf[dp][2*o], vf[dp][2*o+1]);
                }
        }
    }

    const size_t ob = (size_t)b * NTOK * DIMC + h * HD;
    #pragma unroll
    for (int mt = 0; mt < 4; mt++)
        #pragma unroll
        for (int rh = 0; rh < 2; rh++) {
            const int R = mt * 16 + (lane >> 2) + rh * 8;
            if (R < NTOK) {
                #pragma unroll
                for (int dt = 0; dt < 4; dt++) {
                    __half2 hv = __floats2half2_rn(oacc[mt][dt][rh*2],
                                                   oacc[mt][dt][rh*2+1]);
                    const size_t o = ob + (size_t)R * DIMC + dt * 8 + 2 * (lane & 3);
                    *(uint32_t*)(o16 + o) = *(uint32_t*)&hv;
                }
            }
        }
}

// ---------------------------------------------------------------------------
extern "C" void kernel_launch(void* const* d_in, const int* in_sizes, int n_in,
                              void* d_out, int out_size)
{
    const float* x         = (const float*)d_in[0];
    const float* mask      = (const float*)d_in[1];
    const float* qkv_w     = (const float*)d_in[2];
    const float* qkv_b     = (const float*)d_in[3];
    const float* proj_w    = (const float*)d_in[4];
    const float* proj_b    = (const float*)d_in[5];
    const float* rel_table = (const float*)d_in[6];
    const int*   rel_index = (const int*)d_in[7];
    float*       out       = (float*)d_out;

    float* combbuf = nullptr;
    __half *q16, *x16, *a16, *w16;
    cudaGetSymbolAddress((void**)&combbuf, g_comb);
    cudaGetSymbolAddress((void**)&q16, g_q16);
    cudaGetSymbolAddress((void**)&x16, g_x16);
    cudaGetSymbolAddress((void**)&a16, g_a16);
    cudaGetSymbolAddress((void**)&w16, g_w16);

    static int _once = []() {
        cudaFuncSetAttribute(mma_gemm<true, true>,
            cudaFuncAttributeMaxDynamicSharedMemorySize, GEMM_SMEM_BYTES);
        cudaFuncSetAttribute(mma_gemm<false, false>,
            cudaFuncAttributeMaxDynamicSharedMemorySize, GEMM_SMEM_BYTES);
        cudaFuncSetAttribute(attn_mma_kernel,
            cudaFuncAttributeMaxDynamicSharedMemorySize, ATTN_SMEM_BYTES);
        return 0;
    }();
    (void)_once;

    const size_t proj_off = (size_t)QKVN * DIMC;

    prep_w_kernel<<<(QKVN * DIMC + 255) / 256, 256>>>(qkv_w, w16, DIMC, QKVN);
    prep_w_kernel<<<(DIMC * DIMC + 255) / 256, 256>>>(
        proj_w, w16 + proj_off, DIMC, DIMC);
    prep_comb_kernel<<<(NWIN * HEADS * NTOK * 64 + 255) / 256, 256>>>(
        mask, rel_table, rel_index, combbuf);
    {
        const size_t n4 = (size_t)MROWS * DIMC / 4;
        prep_x_kernel<<<(unsigned)((n4 + 255) / 256), 256>>>(x, x16, n4);
    }

    {   // QKV GEMM (fp16 1-MMA, 2-stage, 3 CTAs/SM) -> single fp16 qkv
        dim3 grid(QKVN / 128, MROWS / 128);  // (9, 1568)
        mma_gemm<true, true><<<grid, 256, GEMM_SMEM_BYTES>>>(
            x16, w16, qkv_b, nullptr, q16, MROWS, QKVN, DIMC);
    }

    attn_mma_kernel<<<BWIN * 3, 128, ATTN_SMEM_BYTES>>>(q16, combbuf, a16);

    {   // proj GEMM (fp16 1-MMA) -> fp32 out
        dim3 grid(DIMC / 128, MROWS / 128);  // (3, 1568)
        mma_gemm<false, false><<<grid, 256, GEMM_SMEM_BYTES>>>(
            a16, w16 + proj_off, proj_b, out, nullptr, MROWS, DIMC, DIMC);
    }
}